// round 6
// baseline (speedup 1.0000x reference)
#include <cuda_runtime.h>
#include <cuda_bf16.h>

typedef unsigned long long ull;

#define TT 512
#define BBATCH 512
#define MROWS (TT * BBATCH)

// ---------------- packed f32x2 helpers (sm_103a dual-FP32 pipe) ----------------
__device__ __forceinline__ ull pk2(float lo, float hi) {
    ull r;
    asm("mov.b64 %0, {%1,%2};" : "=l"(r) : "f"(lo), "f"(hi));
    return r;
}
__device__ __forceinline__ void upk2(ull v, float& lo, float& hi) {
    asm("mov.b64 {%0,%1}, %2;" : "=f"(lo), "=f"(hi) : "l"(v));
}
__device__ __forceinline__ ull ffma2(ull a, ull b, ull c) {
    ull d;
    asm("fma.rn.f32x2 %0, %1, %2, %3;" : "=l"(d) : "l"(a), "l"(b), "l"(c));
    return d;
}

__device__ __forceinline__ float sigmf(float x) {
    return __fdividef(1.f, 1.f + __expf(-x));
}
__device__ __forceinline__ float tanh_fast(float x) {
    return 1.f - __fdividef(2.f, __expf(2.f * x) + 1.f);
}

// ---------------- scratch (device globals: no runtime allocation) ----------------
__device__ float g_xg[(size_t)TT * BBATCH * 400];   // reused per layer (max 4*H1)
__device__ float g_h1[(size_t)TT * BBATCH * 100];
__device__ float g_h2[(size_t)TT * BBATCH * 50];
__device__ float g_h3[(size_t)TT * BBATCH * 25];

// ---------------- input GEMM: C[M,N] = A[M,K] @ W[N,K]^T + b1 + b2 ----------------
// Epilogue permutes columns gate-interleaved: logical col n = g*H + h is stored
// at index h*4 + g, so the recurrent kernel reads its 4 gates as one float4.
#define BM 64
#define BN 64
#define BK 16
#define PITCH 68   // float4-aligned, low-conflict STS

template <bool K4>   // K4: K % 4 == 0 -> vectorized A/W loads
__global__ __launch_bounds__(256, 1)
void gemm_bias_kernel(const float* __restrict__ A,
                      const float* __restrict__ W,
                      const float* __restrict__ b1,
                      const float* __restrict__ b2,
                      float* __restrict__ C,
                      int M, int N, int K, int Hq /* = N/4 */) {
    __shared__ float As[BK * PITCH];
    __shared__ float Ws[BK * PITCH];

    const int m0 = blockIdx.x * BM;
    const int n0 = blockIdx.y * BN;
    const int tid = threadIdx.x;
    const int tx = tid & 15;
    const int ty = tid >> 4;
    const int r = ty * 4;
    const int c = tx * 4;

    ull acc[2][4];
#pragma unroll
    for (int p = 0; p < 2; p++)
#pragma unroll
        for (int j = 0; j < 4; j++) acc[p][j] = 0ULL;

    const int ktiles = (K + BK - 1) / BK;
    for (int kt = 0; kt < ktiles; ++kt) {
        const int kbase = kt * BK;
        if (K4) {
            int rr = tid >> 2;            // 0..63
            int kk = (tid & 3) * 4;       // 0,4,8,12
            int kg = kbase + kk;
            float4 va = (kg + 3 < K)
                ? *reinterpret_cast<const float4*>(A + (size_t)(m0 + rr) * K + kg)
                : make_float4(0.f, 0.f, 0.f, 0.f);
            As[(kk + 0) * PITCH + rr] = va.x;
            As[(kk + 1) * PITCH + rr] = va.y;
            As[(kk + 2) * PITCH + rr] = va.z;
            As[(kk + 3) * PITCH + rr] = va.w;
            int cc = rr;
            float4 vw = (kg + 3 < K && (n0 + cc) < N)
                ? *reinterpret_cast<const float4*>(W + (size_t)(n0 + cc) * K + kg)
                : make_float4(0.f, 0.f, 0.f, 0.f);
            Ws[(kk + 0) * PITCH + cc] = vw.x;
            Ws[(kk + 1) * PITCH + cc] = vw.y;
            Ws[(kk + 2) * PITCH + cc] = vw.z;
            Ws[(kk + 3) * PITCH + cc] = vw.w;
        } else {
#pragma unroll
            for (int i = tid; i < BM * BK; i += 256) {
                int rr = i >> 4;
                int kk = i & 15;
                int kg = kbase + kk;
                float va = (kg < K) ? A[(size_t)(m0 + rr) * K + kg] : 0.f;
                As[kk * PITCH + rr] = va;
                int cc = rr;
                float vw = (kg < K && (n0 + cc) < N) ? W[(size_t)(n0 + cc) * K + kg] : 0.f;
                Ws[kk * PITCH + cc] = vw;
            }
        }
        __syncthreads();

#pragma unroll
        for (int k = 0; k < BK; ++k) {
            ull a01 = *reinterpret_cast<const ull*>(As + k * PITCH + r);
            ull a23 = *reinterpret_cast<const ull*>(As + k * PITCH + r + 2);
            float4 bv = *reinterpret_cast<const float4*>(Ws + k * PITCH + c);
            ull bd0 = pk2(bv.x, bv.x);
            ull bd1 = pk2(bv.y, bv.y);
            ull bd2 = pk2(bv.z, bv.z);
            ull bd3 = pk2(bv.w, bv.w);
            acc[0][0] = ffma2(a01, bd0, acc[0][0]);
            acc[1][0] = ffma2(a23, bd0, acc[1][0]);
            acc[0][1] = ffma2(a01, bd1, acc[0][1]);
            acc[1][1] = ffma2(a23, bd1, acc[1][1]);
            acc[0][2] = ffma2(a01, bd2, acc[0][2]);
            acc[1][2] = ffma2(a23, bd2, acc[1][2]);
            acc[0][3] = ffma2(a01, bd3, acc[0][3]);
            acc[1][3] = ffma2(a23, bd3, acc[1][3]);
        }
        __syncthreads();
    }

#pragma unroll
    for (int j = 0; j < 4; ++j) {
        int col = n0 + c + j;
        if (col < N) {
            float bias = __ldg(b1 + col) + __ldg(b2 + col);
            int g = col / Hq;
            int h = col - g * Hq;
            int p = h * 4 + g;                 // gate-interleaved position
            float v0, v1, v2, v3;
            upk2(acc[0][j], v0, v1);
            upk2(acc[1][j], v2, v3);
            size_t base = (size_t)(m0 + r) * N + p;
            C[base]                 = v0 + bias;
            C[base + N]             = v1 + bias;
            C[base + 2 * (size_t)N] = v2 + bias;
            C[base + 3 * (size_t)N] = v3 + bias;
        }
    }
}

// ---------------- recurrent LSTM scan, one layer (fused gates, 1 barrier/step) ----
// Thread (h, b) computes ALL 4 gates for hidden unit h, batch b: gates stay in
// registers, cell state in a register, h double-buffered in SMEM -> one
// __syncthreads per step. xg must be gate-interleaved: xg[t][b][h*4+g].
// k dimension of the packed weight array is padded to Hk (multiple of 4) with
// zero rows, so the 4-wide inner loop never reads out of bounds; the matching
// h-state pad (Hpad >= Hk) is zero in both buffers, so pads contribute 0.
template <int H>
__global__ __launch_bounds__(4 * H, 1)
void lstm_rec_kernel(const float* __restrict__ xg,
                     const float* __restrict__ whh,
                     float* __restrict__ hs) {
    constexpr int FH = 4 * H;
    constexpr int NT = 4 * H;
    constexpr int Hk = (H + 3) & ~3;                    // k-dim padded to /4
    constexpr int Hpad = ((H - 8 + 31) / 32) * 32 + 8;  // Hpad % 32 == 8, >= Hk
    static_assert(Hpad >= Hk, "h-state pad must cover k pad");
    extern __shared__ float sm[];
    float* hsm = sm;                                                     // [2][4][Hpad]
    ulonglong2* wsm2 = reinterpret_cast<ulonglong2*>(sm + 2 * 4 * Hpad); // [Hk][H]

    const int tid = threadIdx.x;
    const int b = tid & 3;
    const int h = tid >> 2;
    const int b0 = blockIdx.x * 4;

    // Pre-pack weights: wsm2[k*H + h] = { pk2(w_i, w_f), pk2(w_g, w_o) } at [h][k];
    // rows k in [H, Hk) are zero.
    for (int i = tid; i < Hk * H; i += NT) {
        int hh = i % H;
        int kk = i / H;
        if (kk < H) {
            float wi = whh[(size_t)(0 * H + hh) * H + kk];
            float wf = whh[(size_t)(1 * H + hh) * H + kk];
            float wg = whh[(size_t)(2 * H + hh) * H + kk];
            float wo = whh[(size_t)(3 * H + hh) * H + kk];
            wsm2[(size_t)kk * H + hh] = make_ulonglong2(pk2(wi, wf), pk2(wg, wo));
        } else {
            wsm2[(size_t)kk * H + hh] = make_ulonglong2(0ULL, 0ULL);
        }
    }
    for (int i = tid; i < 2 * 4 * Hpad; i += NT) hsm[i] = 0.f;
    __syncthreads();

    const float* xgp = xg + ((size_t)(b0 + b)) * FH + (size_t)h * 4;
    const size_t tstride = (size_t)BBATCH * FH;
    float4 nx = *reinterpret_cast<const float4*>(xgp);

    float cst = 0.f;
    int cur = 0;
    float* hs_out_base = hs + (size_t)(b0 + b) * H + h;

    for (int t = 0; t < TT; ++t) {
        ull acc_if = pk2(nx.x, nx.y);
        ull acc_go = pk2(nx.z, nx.w);

        if (t + 1 < TT)
            nx = *reinterpret_cast<const float4*>(xgp + (size_t)(t + 1) * tstride);

        const float* hc = hsm + cur * 4 * Hpad + b * Hpad;
        const ulonglong2* wp = wsm2 + h;

#pragma unroll 4
        for (int k4 = 0; k4 < Hk; k4 += 4) {
            // issue all loads first: 1x LDS.128 (h) + 4x LDS.128 (w) in flight
            float4 hv = *reinterpret_cast<const float4*>(hc + k4);
            ulonglong2 w0 = wp[(size_t)(k4 + 0) * H];
            ulonglong2 w1 = wp[(size_t)(k4 + 1) * H];
            ulonglong2 w2 = wp[(size_t)(k4 + 2) * H];
            ulonglong2 w3 = wp[(size_t)(k4 + 3) * H];
            ull h0 = pk2(hv.x, hv.x);
            ull h1 = pk2(hv.y, hv.y);
            ull h2 = pk2(hv.z, hv.z);
            ull h3 = pk2(hv.w, hv.w);
            acc_if = ffma2(w0.x, h0, acc_if);
            acc_go = ffma2(w0.y, h0, acc_go);
            acc_if = ffma2(w1.x, h1, acc_if);
            acc_go = ffma2(w1.y, h1, acc_go);
            acc_if = ffma2(w2.x, h2, acc_if);
            acc_go = ffma2(w2.y, h2, acc_go);
            acc_if = ffma2(w3.x, h3, acc_if);
            acc_go = ffma2(w3.y, h3, acc_go);
        }

        float gi, gf, gg, go;
        upk2(acc_if, gi, gf);
        upk2(acc_go, gg, go);
        float cc = sigmf(gf) * cst + sigmf(gi) * tanh_fast(gg);
        cst = cc;
        float hout = sigmf(go) * tanh_fast(cc);

        hsm[(cur ^ 1) * 4 * Hpad + b * Hpad + h] = hout;
        hs_out_base[(size_t)t * BBATCH * H] = hout;
        cur ^= 1;
        __syncthreads();
    }
}

// ---------------- final linear: out[m] = h3[m,:25] . w + b ----------------
__global__ __launch_bounds__(256)
void linear_kernel(const float* __restrict__ h3,
                   const float* __restrict__ w,
                   const float* __restrict__ b,
                   float* __restrict__ out, int M) {
    __shared__ float ws[32];
    if (threadIdx.x < 25) ws[threadIdx.x] = w[threadIdx.x];
    __syncthreads();
    int m = blockIdx.x * blockDim.x + threadIdx.x;
    if (m < M) {
        float acc = b[0];
        const float* hp = h3 + (size_t)m * 25;
#pragma unroll
        for (int k = 0; k < 25; ++k) acc += hp[k] * ws[k];
        out[m] = acc;
    }
}

// ---------------- launch ----------------
extern "C" void kernel_launch(void* const* d_in, const int* in_sizes, int n_in,
                              void* d_out, int out_size) {
    const float* x     = (const float*)d_in[0];
    const float* w_ih1 = (const float*)d_in[1];
    const float* w_hh1 = (const float*)d_in[2];
    const float* b_ih1 = (const float*)d_in[3];
    const float* b_hh1 = (const float*)d_in[4];
    const float* w_ih2 = (const float*)d_in[5];
    const float* w_hh2 = (const float*)d_in[6];
    const float* b_ih2 = (const float*)d_in[7];
    const float* b_hh2 = (const float*)d_in[8];
    const float* w_ih3 = (const float*)d_in[9];
    const float* w_hh3 = (const float*)d_in[10];
    const float* b_ih3 = (const float*)d_in[11];
    const float* b_hh3 = (const float*)d_in[12];
    const float* w_lin = (const float*)d_in[13];
    const float* b_lin = (const float*)d_in[14];
    float* out = (float*)d_out;

    float *xg, *h1, *h2, *h3;
    cudaGetSymbolAddress((void**)&xg, g_xg);
    cudaGetSymbolAddress((void**)&h1, g_h1);
    cudaGetSymbolAddress((void**)&h2, g_h2);
    cudaGetSymbolAddress((void**)&h3, g_h3);

    // smem: hsm (2*4*Hpad floats) + packed weights (16 * Hk*H bytes)
    const int smem1 = 2 * 4 * 104 * 4 + 16 * 100 * 100;  // 163328 B (Hk=100)
    const int smem2 = 2 * 4 * 72 * 4  + 16 * 52 * 50;    //  43904 B (Hk=52)
    const int smem3 = 2 * 4 * 40 * 4  + 16 * 28 * 25;    //  12480 B (Hk=28)
    cudaFuncSetAttribute((const void*)lstm_rec_kernel<100>,
                         cudaFuncAttributeMaxDynamicSharedMemorySize, smem1);
    cudaFuncSetAttribute((const void*)lstm_rec_kernel<50>,
                         cudaFuncAttributeMaxDynamicSharedMemorySize, smem2);
    cudaFuncSetAttribute((const void*)lstm_rec_kernel<25>,
                         cudaFuncAttributeMaxDynamicSharedMemorySize, smem3);

    const int M = MROWS;

    // Layer 1 (K=64: vectorized loads)
    gemm_bias_kernel<true><<<dim3(M / BM, (400 + BN - 1) / BN), 256>>>(x, w_ih1, b_ih1, b_hh1, xg, M, 400, 64, 100);
    lstm_rec_kernel<100><<<BBATCH / 4, 400, smem1>>>(xg, w_hh1, h1);
    // Layer 2 (K=100: vectorized loads)
    gemm_bias_kernel<true><<<dim3(M / BM, (200 + BN - 1) / BN), 256>>>(h1, w_ih2, b_ih2, b_hh2, xg, M, 200, 100, 50);
    lstm_rec_kernel<50><<<BBATCH / 4, 200, smem2>>>(xg, w_hh2, h2);
    // Layer 3 (K=50: scalar loads)
    gemm_bias_kernel<false><<<dim3(M / BM, (100 + BN - 1) / BN), 256>>>(h2, w_ih3, b_ih3, b_hh3, xg, M, 100, 50, 25);
    lstm_rec_kernel<25><<<BBATCH / 4, 100, smem3>>>(xg, w_hh3, h3);
    // Output projection
    linear_kernel<<<(M + 255) / 256, 256>>>(h3, w_lin, b_lin, out, M);
}